// round 14
// baseline (speedup 1.0000x reference)
#include <cuda_runtime.h>
#include <cstdint>

// Problem constants (fixed by reference setup_inputs)
#define B_SZ   16
#define T_IN   512
#define D_DIM  768
#define D4     (D_DIM / 4)       // 192 float4 per row = blockDim
#define PH     4                 // phonemes per block
#define NBLK   (T_IN / PH)       // 128 blocks per batch

// FINAL — confirmed across R7/R12/R13: body 18.2-18.9us, total 22.56-22.75us,
// rel_err 0. The body sits at the L2/HBM write-path floor: ~88MB of mandatory
// output writes at ~4.8TB/s effective chip-wide store throughput (~18.5us).
// Ten measured bodies across seven structurally different implementations
// (gather, scatter, fused, TMA bulk, 256-bit v8, predicated unroll, ...) all
// land 17.9-20.7us; every issue-side lever (instruction count, store
// mechanism, read dedupe, prologue, predication, cache hints) was
// individually falsified. Remaining total variance is harness/DVFS noise.
//
// Prologue: thread j<128 loads durations[4j..4j+3] as one int4;
// prefix-before-block = block-reduce of thread-sums for j<blk (exact int4
// boundary); block's own 4 durations = thread j==blk's int4. One barrier.
// durations are int32 on device (JAX default config downgrades int64).
__global__ void __launch_bounds__(D4) lr_fused2_kernel(
    const float4* __restrict__ hidden,
    const int*    __restrict__ durations,
    float4*       __restrict__ out,
    int t_out) {
    __shared__ int s_red_before[4], s_red_all[4];
    __shared__ int s_mydur[PH];

    const int blk  = blockIdx.x;            // 0..NBLK-1
    const int b    = blockIdx.y;
    const int i0   = blk * PH;
    const int tid  = threadIdx.x;           // 0..191
    const int lane = tid & 31;
    const int wid  = tid >> 5;              // 0..5

    // ---- Phase 0: row loads (depend only on blockIdx -> issue immediately) ----
    float4 v[PH];
    #pragma unroll
    for (int k = 0; k < PH; ++k)
        v[k] = __ldg(hidden + ((size_t)b * T_IN + i0 + k) * D4 + tid);

    // ---- Phase 1: duration prefix via one int4 per thread (threads 0..127) ----
    int s_all = 0, s_before = 0;
    if (tid < NBLK) {
        const int4 d = __ldg((const int4*)(durations + b * T_IN) + tid);
        const int s = d.x + d.y + d.z + d.w;
        s_all = s;
        s_before = (tid < blk) ? s : 0;
        if (tid == blk) {
            s_mydur[0] = d.x; s_mydur[1] = d.y;
            s_mydur[2] = d.z; s_mydur[3] = d.w;
        }
    }
    // warp reduce (warps 0..3 hold data; 4,5 contribute zeros)
    #pragma unroll
    for (int off = 16; off > 0; off >>= 1) {
        s_before += __shfl_down_sync(0xFFFFFFFFu, s_before, off);
        s_all    += __shfl_down_sync(0xFFFFFFFFu, s_all, off);
    }
    if (lane == 0 && wid < 4) { s_red_before[wid] = s_before; s_red_all[wid] = s_all; }
    __syncthreads();

    const int base  = s_red_before[0] + s_red_before[1] + s_red_before[2] + s_red_before[3];
    const int total = s_red_all[0] + s_red_all[1] + s_red_all[2] + s_red_all[3];

    // ---- Phase 2: scatter PH rows to their output frame ranges ----
    float4* const out_b = out + (size_t)b * t_out * D4;
    int run = base;
    #pragma unroll
    for (int k = 0; k < PH; ++k) {
        const int dur = s_mydur[k];
        float4* o = out_b + (size_t)run * D4 + tid;
        #pragma unroll 4
        for (int j = 0; j < dur; ++j)
            o[(size_t)j * D4] = v[k];
        run += dur;
    }

    // ---- Phase 3: padding frames [total, t_out), strided across blocks ----
    const float4 z = make_float4(0.f, 0.f, 0.f, 0.f);
    for (int t = total + blk; t < t_out; t += NBLK)
        out_b[(size_t)t * D4 + tid] = z;
}

extern "C" void kernel_launch(void* const* d_in, const int* in_sizes, int n_in,
                              void* d_out, int out_size) {
    const float* hidden    = (const float*)d_in[0];  // (B, T_IN, D) f32
    const int*   durations = (const int*)d_in[1];    // (B, T_IN) int32

    const int t_out = out_size / (B_SZ * D_DIM);

    dim3 grid(NBLK, B_SZ);
    lr_fused2_kernel<<<grid, D4>>>((const float4*)hidden, durations,
                                   (float4*)d_out, t_out);
}

// round 15
// speedup vs baseline: 1.0014x; 1.0014x over previous
#include <cuda_runtime.h>
#include <cstdint>

// Problem constants (fixed by reference setup_inputs)
#define B_SZ   16
#define T_IN   512
#define D_DIM  768
#define D4     (D_DIM / 4)       // 192 float4 per row = blockDim
#define PH     4                 // phonemes per block
#define NBLK   (T_IN / PH)       // 128 blocks per batch

// FINAL — confirmed across R7/R12/R13/R14: body 18.2-18.9us, total
// 22.56-22.75us, rel_err 0. The body sits at the L2/HBM write-path floor:
// ~88MB of mandatory output writes at ~4.8TB/s effective chip-wide store
// throughput (~18.5us). Ten measured bodies across seven structurally
// different implementations (gather, scatter, fused, TMA bulk, 256-bit v8,
// predicated unroll, ...) all land 17.9-20.7us; every issue-side lever
// (instruction count, store mechanism, read dedupe, prologue, predication,
// cache hints) was individually falsified. Remaining variance is
// harness/DVFS noise.
//
// Prologue: thread j<128 loads durations[4j..4j+3] as one int4;
// prefix-before-block = block-reduce of thread-sums for j<blk (exact int4
// boundary); block's own 4 durations = thread j==blk's int4. One barrier.
// durations are int32 on device (JAX default config downgrades int64).
__global__ void __launch_bounds__(D4) lr_fused2_kernel(
    const float4* __restrict__ hidden,
    const int*    __restrict__ durations,
    float4*       __restrict__ out,
    int t_out) {
    __shared__ int s_red_before[4], s_red_all[4];
    __shared__ int s_mydur[PH];

    const int blk  = blockIdx.x;            // 0..NBLK-1
    const int b    = blockIdx.y;
    const int i0   = blk * PH;
    const int tid  = threadIdx.x;           // 0..191
    const int lane = tid & 31;
    const int wid  = tid >> 5;              // 0..5

    // ---- Phase 0: row loads (depend only on blockIdx -> issue immediately) ----
    float4 v[PH];
    #pragma unroll
    for (int k = 0; k < PH; ++k)
        v[k] = __ldg(hidden + ((size_t)b * T_IN + i0 + k) * D4 + tid);

    // ---- Phase 1: duration prefix via one int4 per thread (threads 0..127) ----
    int s_all = 0, s_before = 0;
    if (tid < NBLK) {
        const int4 d = __ldg((const int4*)(durations + b * T_IN) + tid);
        const int s = d.x + d.y + d.z + d.w;
        s_all = s;
        s_before = (tid < blk) ? s : 0;
        if (tid == blk) {
            s_mydur[0] = d.x; s_mydur[1] = d.y;
            s_mydur[2] = d.z; s_mydur[3] = d.w;
        }
    }
    // warp reduce (warps 0..3 hold data; 4,5 contribute zeros)
    #pragma unroll
    for (int off = 16; off > 0; off >>= 1) {
        s_before += __shfl_down_sync(0xFFFFFFFFu, s_before, off);
        s_all    += __shfl_down_sync(0xFFFFFFFFu, s_all, off);
    }
    if (lane == 0 && wid < 4) { s_red_before[wid] = s_before; s_red_all[wid] = s_all; }
    __syncthreads();

    const int base  = s_red_before[0] + s_red_before[1] + s_red_before[2] + s_red_before[3];
    const int total = s_red_all[0] + s_red_all[1] + s_red_all[2] + s_red_all[3];

    // ---- Phase 2: scatter PH rows to their output frame ranges ----
    float4* const out_b = out + (size_t)b * t_out * D4;
    int run = base;
    #pragma unroll
    for (int k = 0; k < PH; ++k) {
        const int dur = s_mydur[k];
        float4* o = out_b + (size_t)run * D4 + tid;
        #pragma unroll 4
        for (int j = 0; j < dur; ++j)
            o[(size_t)j * D4] = v[k];
        run += dur;
    }

    // ---- Phase 3: padding frames [total, t_out), strided across blocks ----
    const float4 z = make_float4(0.f, 0.f, 0.f, 0.f);
    for (int t = total + blk; t < t_out; t += NBLK)
        out_b[(size_t)t * D4 + tid] = z;
}

extern "C" void kernel_launch(void* const* d_in, const int* in_sizes, int n_in,
                              void* d_out, int out_size) {
    const float* hidden    = (const float*)d_in[0];  // (B, T_IN, D) f32
    const int*   durations = (const int*)d_in[1];    // (B, T_IN) int32

    const int t_out = out_size / (B_SZ * D_DIM);

    dim3 grid(NBLK, B_SZ);
    lr_fused2_kernel<<<grid, D4>>>((const float4*)hidden, durations,
                                   (float4*)d_out, t_out);
}